// round 16
// baseline (speedup 1.0000x reference)
#include <cuda_runtime.h>
#include <cuda_fp16.h>
#include <math.h>
#include <stdint.h>

// ---------------- problem constants ----------------
#define BATCH 128
#define EMB   384
#define NTOK  197
#define NPATCH 196
#define HEADS 6
#define HD    64
#define HID   1536
#define NE    4
#define NCLS  1000
#define MTOK  (BATCH*NTOK)      // 25216
#define MPATCH (BATCH*NPATCH)   // 25088
#define SSTR  40                // smem row stride in halves
#define TSZ   (128*SSTR)        // one tile array in halves (5120)
#define NSTAGE 3
#define STG_BYTES (2*TSZ*2)     // 20480 B per stage (A, B)
#define SMEM_GEMM (NSTAGE*STG_BYTES)  // 61440 B
#define MOE_TOK 8

// ---------------- scratch (static device globals; no allocation) ----------------
__device__ __half g_tokh[MTOK*EMB];            // tokens + pos embed, fp16
__device__ __half g_hnh[MTOK*EMB];             // LN output, fp16
__device__ __half g_xh [MPATCH*768];           // im2col x, fp16
__device__ __half g_cwh[EMB*768];              // conv_w fp16
__device__ __half g_wkh[768*EMB];              // in_proj_w K/V rows fp16
__device__ __half g_kvh[MTOK*768];             // K/V output, fp16
__device__ float g_h2 [BATCH*EMB];
__device__ float g_hid[256*HID];
__device__ float g_p2 [4*256*EMB];
__device__ int   g_ecnt[NE];
__device__ int   g_elist[NE*256];

__device__ __forceinline__ float warp_sum(float v) {
#pragma unroll
    for (int o = 16; o > 0; o >>= 1) v += __shfl_down_sync(0xffffffffu, v, o);
    return v;
}
__device__ __forceinline__ float warp_allsum(float v) {
#pragma unroll
    for (int o = 16; o > 0; o >>= 1) v += __shfl_xor_sync(0xffffffffu, v, o);
    return v;
}
__device__ __forceinline__ float warp_allmax(float v) {
#pragma unroll
    for (int o = 16; o > 0; o >>= 1) v = fmaxf(v, __shfl_xor_sync(0xffffffffu, v, o));
    return v;
}
__device__ __forceinline__ float gelu_exact(float v) {
    return 0.5f * v * (1.0f + erff(v * 0.70710678118654752f));
}
__device__ __forceinline__ uint32_t smem_u32(const void* p) {
    uint32_t a;
    asm("{ .reg .u64 t; cvta.to.shared.u64 t, %1; cvt.u32.u64 %0, t; }" : "=r"(a) : "l"(p));
    return a;
}

// mma.sync m16n8k16 fp16 -> f32
__device__ __forceinline__ void mma_f16(float* c, const uint32_t* a, const uint32_t* b) {
    asm volatile(
        "mma.sync.aligned.m16n8k16.row.col.f32.f16.f16.f32 "
        "{%0,%1,%2,%3}, {%4,%5,%6,%7}, {%8,%9}, {%0,%1,%2,%3};"
        : "+f"(c[0]), "+f"(c[1]), "+f"(c[2]), "+f"(c[3])
        : "r"(a[0]), "r"(a[1]), "r"(a[2]), "r"(a[3]), "r"(b[0]), "r"(b[1]));
}
__device__ __forceinline__ void ldsm4(uint32_t* r, uint32_t addr) {
    asm volatile("ldmatrix.sync.aligned.m8n8.x4.shared.b16 {%0,%1,%2,%3}, [%4];"
        : "=r"(r[0]), "=r"(r[1]), "=r"(r[2]), "=r"(r[3]) : "r"(addr));
}
__device__ __forceinline__ void cpa16(uint32_t dst, const void* src) {
    asm volatile("cp.async.cg.shared.global [%0], [%1], 16;" :: "r"(dst), "l"(src));
}
#define CP_COMMIT() asm volatile("cp.async.commit_group;" ::: "memory")
template<int N> __device__ __forceinline__ void cp_wait() {
    asm volatile("cp.async.wait_group %0;" :: "n"(N) : "memory");
}

// pack fp32x4 -> fp16x4
__device__ __forceinline__ uint2 pack4_h(float4 v) {
    uint2 hp;
    __half h0 = __float2half_rn(v.x), h1 = __float2half_rn(v.y);
    __half h2 = __float2half_rn(v.z), h3 = __float2half_rn(v.w);
    hp.x = ((uint32_t)__half_as_ushort(h1) << 16) | __half_as_ushort(h0);
    hp.y = ((uint32_t)__half_as_ushort(h3) << 16) | __half_as_ushort(h2);
    return hp;
}
__device__ __forceinline__ float4 unpack4_h(uint2 hp) {
    float4 v;
    v.x = __half2float(__ushort_as_half((unsigned short)(hp.x & 0xFFFF)));
    v.y = __half2float(__ushort_as_half((unsigned short)(hp.x >> 16)));
    v.z = __half2float(__ushort_as_half((unsigned short)(hp.y & 0xFFFF)));
    v.w = __half2float(__ushort_as_half((unsigned short)(hp.y >> 16)));
    return v;
}

// ---------------- KXW: im2col x + weight conversion + cls init, one launch ----------------
#define N4X (MPATCH*768/4)
#define CW4 (EMB*768/4)
#define WK4 (768*EMB/4)
#define CLS4 (BATCH*EMB/4)
__global__ void __launch_bounds__(256) kxw_prep(const float* __restrict__ x,
                                                const float* __restrict__ convw,
                                                const float* __restrict__ inprojw,
                                                const float* __restrict__ cls,
                                                const float* __restrict__ pos) {
    int idx = blockIdx.x*256 + threadIdx.x;
    if (idx < N4X) {
        int fi = idx*4;
        int w  = fi % 224;
        int t1 = fi / 224;
        int h  = t1 % 224;
        int cb = t1 / 224;
        int c  = cb % 3, b = cb / 3;
        float4 v = *(const float4*)&x[fi];
        int px = w >> 4, j = w & 15, py = h >> 4, i = h & 15;
        int r = b*NPATCH + py*14 + px;
        int k = c*256 + i*16 + j;
        *(uint2*)&g_xh[(size_t)r*768 + k] = pack4_h(v);
        return;
    }
    int i = idx - N4X;
    if (i < CW4) {
        ((uint2*)g_cwh)[i] = pack4_h(((const float4*)convw)[i]);
        return;
    }
    int j = i - CW4;
    if (j < WK4) {
        ((uint2*)g_wkh)[j] = pack4_h(((const float4*)(inprojw + 384*EMB))[j]);
        return;
    }
    int m = j - WK4;
    if (m < CLS4) {
        int b = m / (EMB/4);
        int e4 = m % (EMB/4);
        float4 cv = ((const float4*)cls)[e4];
        float4 pv = ((const float4*)pos)[e4];
        float4 o;
        o.x = cv.x + pv.x; o.y = cv.y + pv.y; o.z = cv.z + pv.z; o.w = cv.w + pv.w;
        ((uint2*)&g_tokh[(size_t)(b*NTOK)*EMB])[e4] = pack4_h(o);
        if (m < NE) g_ecnt[m] = 0;
    }
}

// ============ HMMA GEMM: 128x128 block, 512 thr / 16 warps (4x4, 32x32 warp tile),
// ============ K-chunk 32, fp16 operands, 3-stage cp.async, 2 CTAs/SM ============

struct GemmCtx {
    int lane, warp, wm, wn;
    uint32_t smb, aoff[2], boff[2];
    int crow, ccol;
};
__device__ __forceinline__ void gemm_init(GemmCtx& g, const void* sm) {
    int tid = threadIdx.x;
    g.lane = tid & 31; g.warp = tid >> 5;
    g.wm = g.warp & 3; g.wn = g.warp >> 2;
    g.smb = smem_u32(sm);
    int r_in = g.lane & 7, g8 = g.lane >> 3;
#pragma unroll
    for (int mf = 0; mf < 2; mf++)
        g.aoff[mf] = ((g.wm*32 + mf*16 + r_in + ((g8 & 1) << 3))*SSTR + ((g8 >> 1) << 3)) * 2;
#pragma unroll
    for (int j = 0; j < 2; j++)
        g.boff[j] = ((g.wn*32 + j*16 + r_in + ((g8 >> 1) << 3))*SSTR + ((g8 & 1) << 3)) * 2;
    g.crow = tid >> 2;
    g.ccol = (tid & 3) * 8;
}
__device__ __forceinline__ void gemm_copy(const GemmCtx& g, int stage,
        const __half* A, size_t a_str, const __half* B, size_t b_str, int k0) {
    uint32_t st = g.smb + (uint32_t)stage*STG_BYTES;
    uint32_t sdst = (uint32_t)(g.crow*SSTR + g.ccol)*2;
    cpa16(st +           sdst, A + (size_t)g.crow*a_str + k0 + g.ccol);
    cpa16(st + 1*TSZ*2 + sdst, B + (size_t)g.crow*b_str + k0 + g.ccol);
    CP_COMMIT();
}
__device__ __forceinline__ void gemm_compute(const GemmCtx& g, int stage, float acc[2][4][4]) {
    uint32_t st = g.smb + (uint32_t)stage*STG_BYTES;
    uint32_t a_b = st, b_b = st + 1*TSZ*2;
#pragma unroll
    for (int kb = 0; kb < 32; kb += 16) {
        uint32_t kbo = kb * 2;
        uint32_t a[2][4], bfr[2][4];
#pragma unroll
        for (int mf = 0; mf < 2; mf++) ldsm4(a[mf], a_b + g.aoff[mf] + kbo);
#pragma unroll
        for (int j = 0; j < 2; j++) ldsm4(bfr[j], b_b + g.boff[j] + kbo);
#pragma unroll
        for (int mf = 0; mf < 2; mf++)
#pragma unroll
            for (int nf = 0; nf < 4; nf++)
                mma_f16(acc[mf][nf], a[mf], &bfr[nf>>1][(nf&1)*2]);
    }
}

// ---------------- K1: patch-embed GEMM on im2col x, fp16 tok output ----------------
__global__ void __launch_bounds__(512, 2) k1_patch_mma(
        const float* __restrict__ convb, const float* __restrict__ pos) {
    extern __shared__ __half sm[];
    GemmCtx g; gemm_init(g, sm);
    int tileM = blockIdx.x * 128;
    int tileN = blockIdx.y * 128;
    const __half *A = g_xh + (size_t)tileM*768;
    const __half *B = g_cwh + (size_t)tileN*768;
    float acc[2][4][4] = {};
    const int C = 24;
    gemm_copy(g, 0, A, 768, B, 768, 0);
    gemm_copy(g, 1, A, 768, B, 768, 32);
    for (int ch = 0; ch < C; ch++) {
        if (ch == C-1) cp_wait<0>(); else cp_wait<1>();
        __syncthreads();
        if (ch + NSTAGE - 1 < C)
            gemm_copy(g, (ch + NSTAGE - 1) % NSTAGE, A, 768, B, 768, (ch + NSTAGE - 1)*32);
        gemm_compute(g, ch % NSTAGE, acc);
    }
#pragma unroll
    for (int mf = 0; mf < 2; mf++) {
#pragma unroll
        for (int nf = 0; nf < 4; nf++) {
            int n = tileN + g.wn*32 + nf*8 + (g.lane & 3)*2;
            float cb0 = convb[n], cb1 = convb[n+1];
#pragma unroll
            for (int h = 0; h < 2; h++) {
                int R = tileM + g.wm*32 + mf*16 + (g.lane >> 2) + h*8;
                int b = R / NPATCH, p = R % NPATCH;
                int tok = b*NTOK + 1 + p;
                float ox = acc[mf][nf][2*h]   + cb0 + pos[(1+p)*EMB + n];
                float oy = acc[mf][nf][2*h+1] + cb1 + pos[(1+p)*EMB + n + 1];
                *(__half2*)&g_tokh[(size_t)tok*EMB + n] = __floats2half2_rn(ox, oy);
            }
        }
    }
}

// ---------------- K3: K/V projection GEMM, fp16 output. M=25216, N=768, K=384 -------------
__global__ void __launch_bounds__(512, 2) k3_kv_mma(const float* __restrict__ bias) {
    extern __shared__ __half sm[];
    GemmCtx g; gemm_init(g, sm);
    int tileM = blockIdx.x * 128;
    int tileN = blockIdx.y * 128;
    const __half *A = g_hnh + (size_t)tileM*EMB;
    const __half *B = g_wkh + (size_t)tileN*EMB;
    float acc[2][4][4] = {};
    const int C = 12;
    gemm_copy(g, 0, A, EMB, B, EMB, 0);
    gemm_copy(g, 1, A, EMB, B, EMB, 32);
    for (int ch = 0; ch < C; ch++) {
        if (ch == C-1) cp_wait<0>(); else cp_wait<1>();
        __syncthreads();
        if (ch + NSTAGE - 1 < C)
            gemm_copy(g, (ch + NSTAGE - 1) % NSTAGE, A, EMB, B, EMB, (ch + NSTAGE - 1)*32);
        gemm_compute(g, ch % NSTAGE, acc);
    }
#pragma unroll
    for (int mf = 0; mf < 2; mf++) {
#pragma unroll
        for (int nf = 0; nf < 4; nf++) {
            int n = tileN + g.wn*32 + nf*8 + (g.lane & 3)*2;
            float b0 = bias[384 + n], b1v = bias[384 + n + 1];
#pragma unroll
            for (int h = 0; h < 2; h++) {
                int R = tileM + g.wm*32 + mf*16 + (g.lane >> 2) + h*8;
                *(__half2*)&g_kvh[(size_t)R*768 + n] =
                    __floats2half2_rn(acc[mf][nf][2*h] + b0, acc[mf][nf][2*h+1] + b1v);
            }
        }
    }
}

// ---------------- K2: LayerNorm, warp per token, fp16 in / fp16 out ----------------
__global__ void __launch_bounds__(256) k2_ln(const float* __restrict__ g,
                                             const float* __restrict__ bt) {
    int t = blockIdx.x * 8 + (threadIdx.x >> 5);
    int lane = threadIdx.x & 31;
    const uint2* in = (const uint2*)(g_tokh + (size_t)t*EMB);
    float4 v[3];
    float s = 0.f, q = 0.f;
#pragma unroll
    for (int j = 0; j < 3; j++) {
        v[j] = unpack4_h(in[lane + 32*j]);
        s += v[j].x + v[j].y + v[j].z + v[j].w;
        q += v[j].x*v[j].x + v[j].y*v[j].y + v[j].z*v[j].z + v[j].w*v[j].w;
    }
    s = warp_allsum(s); q = warp_allsum(q);
    float m = s * (1.0f/EMB);
    float r = rsqrtf(q*(1.0f/EMB) - m*m + 1e-5f);
#pragma unroll
    for (int j = 0; j < 3; j++) {
        float4 gg = ((const float4*)g)[lane + 32*j];
        float4 bb = ((const float4*)bt)[lane + 32*j];
        float4 o;
        o.x = (v[j].x - m)*r*gg.x + bb.x;
        o.y = (v[j].y - m)*r*gg.y + bb.y;
        o.z = (v[j].z - m)*r*gg.z + bb.z;
        o.w = (v[j].w - m)*r*gg.w + bb.w;
        *(uint2*)&g_hnh[(size_t)t*EMB + 4*(lane + 32*j)] = pack4_h(o);
    }
}

// ---------------- K456: q-proj + attention + out_proj + LN + router (fused, block per b) ---
__global__ void __launch_bounds__(EMB) k456_attn(
        const float* __restrict__ W,  const float* __restrict__ bias,
        const float* __restrict__ Wo, const float* __restrict__ bo,
        const float* __restrict__ g1, const float* __restrict__ b1,
        const float* __restrict__ rw, const float* __restrict__ rb) {
    int b = blockIdx.x;
    int tid = threadIdx.x;                        // 384 = 12 warps
    int w = tid >> 5, l = tid & 31;
    __shared__ float hs[EMB], qsm[EMB], osm[EMB], h2s[EMB];
    __shared__ float sc[HEADS][NTOK+1];
    __shared__ float inv_s[HEADS];
    __shared__ float rsx[12], rqx[12];
    __shared__ float lg[NE];
    __shared__ float mm, rr;

    hs[tid] = __half2float(g_hnh[(size_t)(b*NTOK)*EMB + tid]);
    __syncthreads();

    // ---- q projection (thread per output) ----
    {
        float acc = bias[tid];
        const float4* Wr = (const float4*)(W + (size_t)tid*EMB);
#pragma unroll 8
        for (int k = 0; k < 96; k++) {
            float4 wv = Wr[k];
            acc += hs[4*k]*wv.x + hs[4*k+1]*wv.y + hs[4*k+2]*wv.z + hs[4*k+3]*wv.w;
        }
        qsm[tid] = acc;
    }
    __syncthreads();

    // ---- scores: 6 heads x 197 keys ----
    const __half* kvb = g_kvh + (size_t)b*NTOK*768;
    for (int idx = tid; idx < HEADS*NTOK; idx += EMB) {
        int h = idx / NTOK, j = idx % NTOK;
        const __half2* kr = (const __half2*)(kvb + j*768 + h*HD);
        const float* qh = qsm + h*HD;
        float p = 0.f;
#pragma unroll
        for (int d = 0; d < 32; d++) {
            float2 kv2 = __half22float2(kr[d]);
            p += qh[2*d]*kv2.x + qh[2*d+1]*kv2.y;
        }
        sc[h][j] = p * 0.125f;
    }
    __syncthreads();

    // ---- softmax per head (warp per head) ----
    if (w < HEADS) {
        float mx = -1e30f;
        for (int j = l; j < NTOK; j += 32) mx = fmaxf(mx, sc[w][j]);
        mx = warp_allmax(mx);
        float sm = 0.f;
        for (int j = l; j < NTOK; j += 32) { float e = expf(sc[w][j] - mx); sc[w][j] = e; sm += e; }
        sm = warp_allsum(sm);
        if (l == 0) inv_s[w] = 1.0f / sm;
    }
    __syncthreads();

    // ---- o = P @ V, coalesced: thread owns V column tid; per key read contiguous row ----
    {
        int h = tid >> 6;
        const __half* vb = kvb + 384 + tid;      // V[j] at vb + j*768
        const float* ph = sc[h];
        float o = 0.f;
        int j = 0;
#pragma unroll 4
        for (; j + 4 <= NTOK; j += 4) {
            o += ph[j]  *__half2float(vb[(size_t)(j  )*768]);
            o += ph[j+1]*__half2float(vb[(size_t)(j+1)*768]);
            o += ph[j+2]*__half2float(vb[(size_t)(j+2)*768]);
            o += ph[j+3]*__half2float(vb[(size_t)(j+3)*768]);
        }
        for (; j < NTOK; j++) o += ph[j]*__half2float(vb[(size_t)j*768]);
        osm[tid] = o * inv_s[h];
    }
    __syncthreads();

    // ---- out_proj + LN + router + top-2 ----
    float acc = bo[tid];
    {
        const float4* Wr = (const float4*)(Wo + (size_t)tid*EMB);
#pragma unroll 8
        for (int k = 0; k < 96; k++) {
            float4 wv = Wr[k];
            acc += osm[4*k]*wv.x + osm[4*k+1]*wv.y + osm[4*k+2]*wv.z + osm[4*k+3]*wv.w;
        }
    }
    float s = warp_sum(acc), q = warp_sum(acc*acc);
    if (l == 0) { rsx[w] = s; rqx[w] = q; }
    __syncthreads();
    if (tid == 0) {
        float S = 0.f, Q = 0.f;
#pragma unroll
        for (int i = 0; i < 12; i++) { S += rsx[i]; Q += rqx[i]; }
        float m = S*(1.0f/EMB);
        mm = m; rr = rsqrtf(Q*(1.0f/EMB) - m*m + 1e-5f);
    }
    __syncthreads();
    float h2 = (acc-mm)*rr*g1[tid] + b1[tid];
    g_h2[b*EMB + tid] = h2;
    h2s[tid] = h2;
    __syncthreads();
    if (w < NE) {
        float p = 0.f;
        for (int e = l; e < EMB; e += 32) p += h2s[e]*rw[w*EMB + e];
        p = warp_sum(p);
        if (l == 0) lg[w] = p + rb[w];
    }
    __syncthreads();
    if (tid == 0) {
        int i1 = 0;
        for (int i = 1; i < NE; i++) if (lg[i] > lg[i1]) i1 = i;
        int i2 = -1;
        for (int i = 0; i < NE; i++) {
            if (i == i1) continue;
            if (i2 < 0 || lg[i] > lg[i2]) i2 = i;
        }
        int p1 = atomicAdd(&g_ecnt[i1], 1);
        g_elist[i1*256 + p1] = b*2;
        int p2 = atomicAdd(&g_ecnt[i2], 1);
        g_elist[i2*256 + p2] = b*2 + 1;
    }
}

// ---------------- K8a: MoE phase 1, hid = gelu(h@W1+b1), sliced over HID ----------------
__global__ void __launch_bounds__(EMB) k8a_moe(
        const float* __restrict__ ew1, const float* __restrict__ eb1) {
    int e = blockIdx.x;
    int tile = blockIdx.y;
    int slice = blockIdx.z;
    int n = g_ecnt[e];
    int t0 = tile * MOE_TOK;
    if (t0 >= n) return;
    int nt = min(MOE_TOK, n - t0);

    __shared__ float hsT[EMB][MOE_TOK];
    __shared__ int ent[MOE_TOK];
    int tid = threadIdx.x;
    if (tid < MOE_TOK)
        ent[tid] = g_elist[e*256 + t0 + ((tid < nt) ? tid : 0)];
    __syncthreads();
#pragma unroll
    for (int tt = 0; tt < MOE_TOK; tt++)
        hsT[tid][tt] = g_h2[(ent[tt] >> 1)*EMB + tid];
    __syncthreads();

    int c = slice*384 + tid;
    const float* W1 = ew1 + (size_t)e*EMB*HID + c;
    float b1v = eb1[e*HID + c];
    float acc[MOE_TOK];
#pragma unroll
    for (int tt = 0; tt < MOE_TOK; tt++) acc[tt] = b1v;
#pragma unroll 4
    for (int k = 0; k < EMB; k++) {
        float w = W1[(size_t)k*HID];
        float4 h0 = *(const float4*)&hsT[k][0];
        float4 h1 = *(const float4*)&hsT[k][4];
        acc[0] += h0.x*w; acc[1] += h0.y*w; acc[2] += h0.z*w; acc[3] += h0.w*w;
        acc[4] += h1.x*w; acc[5] += h1.y*w; acc[6] += h1.z*w; acc[7] += h1.w*w;
    }
#pragma unroll
    for (int tt = 0; tt < MOE_TOK; tt++)
        if (tt < nt)
            g_hid[(size_t)ent[tt]*HID + c] = gelu_exact(acc[tt]);
}

// ---------------- K8b: MoE phase 2, out partials = hid@W2 sliced over HID-k ----------------
__global__ void __launch_bounds__(EMB) k8b_moe(
        const float* __restrict__ ew2, const float* __restrict__ eb2) {
    int e = blockIdx.x;
    int tile = blockIdx.y;
    int slice = blockIdx.z;
    int n = g_ecnt[e];
    int t0 = tile * MOE_TOK;
    if (t0 >= n) return;
    int nt = min(MOE_TOK, n - t0);

    __shared__ float hidT[384][MOE_TOK];
    __shared__ int ent[MOE_TOK];
    int tid = threadIdx.x;
    if (tid < MOE_TOK)
        ent[tid] = g_elist[e*256 + t0 + ((tid < nt) ? tid : 0)];
    __syncthreads();
#pragma unroll
    for (int tt = 0; tt < MOE_TOK; tt++)
        hidT[tid][tt] = g_hid[(size_t)ent[tt]*HID + slice*384 + tid];
    __syncthreads();

    const float* W2 = ew2 + (size_t)e*HID*EMB + (size_t)slice*384*EMB + tid;
    float acc[MOE_TOK] = {};
#pragma unroll 4
    for (int k = 0; k < 384; k++) {
        float w = W2[(size_t)k*EMB];
        float4 h0 = *(const float4*)&hidT[k][0];
        float4 h1 = *(const float4*)&hidT[k][4];
        acc[0] += h0.x*w; acc[1] += h0.y*w; acc[2] += h0.z*w; acc[3] += h0.w*w;
        acc[4] += h1.x*w; acc[5] += h1.y*w; acc[6] += h1.z*w; acc[7] += h1.w*w;
    }
    float b2v = (slice == 0) ? eb2[e*EMB + tid] : 0.f;
#pragma unroll
    for (int tt = 0; tt < MOE_TOK; tt++)
        if (tt < nt)
            g_p2[(size_t)slice*(256*EMB) + ent[tt]*EMB + tid] = 0.5f * (acc[tt] + b2v);
}

// ---------------- K9: LN2 + classification head, 4 tokens/block, class-sliced ----------------
#define K9_TOK 4
__global__ void __launch_bounds__(EMB) k9_head(
        const float* __restrict__ g2, const float* __restrict__ b2,
        const float* __restrict__ Wh, const float* __restrict__ bh,
        float* __restrict__ out) {
    int b0 = blockIdx.x * K9_TOK;
    int cblk = blockIdx.y;
    int tid = threadIdx.x;
    __shared__ float hl[K9_TOK][EMB];
    __shared__ float rsx[K9_TOK][12], rqx[K9_TOK][12];
    __shared__ float mm[K9_TOK], rr[K9_TOK];
    int w = tid >> 5, l = tid & 31;
    float v[K9_TOK];
#pragma unroll
    for (int tt = 0; tt < K9_TOK; tt++) {
        int b = b0 + tt;
        float sum = 0.f;
#pragma unroll
        for (int s = 0; s < 4; s++)
            sum += g_p2[(size_t)s*(256*EMB) + (b*2)*EMB + tid]
                 + g_p2[(size_t)s*(256*EMB) + (b*2+1)*EMB + tid];
        v[tt] = sum;
        float sv = warp_sum(sum), qv = warp_sum(sum*sum);
        if (l == 0) { rsx[tt][w] = sv; rqx[tt][w] = qv; }
    }
    __syncthreads();
    if (tid < K9_TOK) {
        float S = 0.f, Q = 0.f;
#pragma unroll
        for (int i = 0; i < 12; i++) { S += rsx[tid][i]; Q += rqx[tid][i]; }
        float m = S*(1.0f/EMB);
        mm[tid] = m; rr[tid] = rsqrtf(Q*(1.0f/EMB) - m*m + 1e-5f);
    }
    __syncthreads();
    float gv = g2[tid], bv = b2[tid];
#pragma unroll
    for (int tt = 0; tt < K9_TOK; tt++)
        hl[tt][tid] = (v[tt]-mm[tt])*rr[tt]*gv + bv;
    __syncthreads();
    int c = cblk*384 + tid;
    if (c < NCLS) {
        float acc[K9_TOK];
        float bhc = bh[c];
#pragma unroll
        for (int tt = 0; tt < K9_TOK; tt++) acc[tt] = bhc;
        const float4* Wr = (const float4*)(Wh + (size_t)c*EMB);
#pragma unroll 4
        for (int k = 0; k < 96; k++) {
            float4 wv = Wr[k];
#pragma unroll
            for (int tt = 0; tt < K9_TOK; tt++)
                acc[tt] += hl[tt][4*k]*wv.x + hl[tt][4*k+1]*wv.y
                         + hl[tt][4*k+2]*wv.z + hl[tt][4*k+3]*wv.w;
        }
#pragma unroll
        for (int tt = 0; tt < K9_TOK; tt++)
            out[(b0+tt)*NCLS + c] = acc[tt];
    }
}

// ---------------- launcher ----------------
extern "C" void kernel_launch(void* const* d_in, const int* in_sizes, int n_in,
                              void* d_out, int out_size) {
    const float* x         = (const float*)d_in[0];
    const float* conv_w    = (const float*)d_in[1];
    const float* conv_b    = (const float*)d_in[2];
    const float* cls_token = (const float*)d_in[3];
    const float* pos_embed = (const float*)d_in[4];
    const float* ln1_g     = (const float*)d_in[5];
    const float* ln1_b     = (const float*)d_in[6];
    const float* in_proj_w = (const float*)d_in[7];
    const float* in_proj_b = (const float*)d_in[8];
    const float* out_proj_w= (const float*)d_in[9];
    const float* out_proj_b= (const float*)d_in[10];
    const float* router_w  = (const float*)d_in[11];
    const float* router_b  = (const float*)d_in[12];
    const float* ew1       = (const float*)d_in[13];
    const float* eb1       = (const float*)d_in[14];
    const float* ew2       = (const float*)d_in[15];
    const float* eb2       = (const float*)d_in[16];
    const float* ln2_g     = (const float*)d_in[17];
    const float* ln2_b     = (const float*)d_in[18];
    const float* head_w    = (const float*)d_in[19];
    const float* head_b    = (const float*)d_in[20];
    float* out = (float*)d_out;

    cudaFuncSetAttribute(k1_patch_mma, cudaFuncAttributeMaxDynamicSharedMemorySize, SMEM_GEMM);
    cudaFuncSetAttribute(k3_kv_mma,    cudaFuncAttributeMaxDynamicSharedMemorySize, SMEM_GEMM);

    kxw_prep<<<(N4X + CW4 + WK4 + CLS4 + 255)/256, 256>>>(x, conv_w, in_proj_w, cls_token, pos_embed);
    k1_patch_mma<<<dim3(MPATCH/128, EMB/128), 512, SMEM_GEMM>>>(conv_b, pos_embed);
    k2_ln<<<MTOK/8, 256>>>(ln1_g, ln1_b);
    k3_kv_mma<<<dim3(MTOK/128, 768/128), 512, SMEM_GEMM>>>(in_proj_b);
    k456_attn<<<BATCH, EMB>>>(in_proj_w, in_proj_b, out_proj_w, out_proj_b,
                              ln1_g, ln1_b, router_w, router_b);
    k8a_moe<<<dim3(NE, 256/MOE_TOK, 4), EMB>>>(ew1, eb1);
    k8b_moe<<<dim3(NE, 256/MOE_TOK, 4), EMB>>>(ew2, eb2);
    k9_head<<<dim3(BATCH/K9_TOK, 3), EMB>>>(ln2_g, ln2_b, head_w, head_b, out);
}

// round 17
// speedup vs baseline: 1.1445x; 1.1445x over previous
#include <cuda_runtime.h>
#include <cuda_fp16.h>
#include <math.h>
#include <stdint.h>

// ---------------- problem constants ----------------
#define BATCH 128
#define EMB   384
#define NTOK  197
#define NPATCH 196
#define HEADS 6
#define HD    64
#define HID   1536
#define NE    4
#define NCLS  1000
#define MTOK  (BATCH*NTOK)      // 25216
#define MPATCH (BATCH*NPATCH)   // 25088
#define SSTR  40                // smem row stride in halves
#define TSZ   (128*SSTR)        // one tile array in halves (5120)
#define NSTAGE 3
#define STG_BYTES (2*TSZ*2)     // 20480 B per stage (A, B)
#define SMEM_GEMM (NSTAGE*STG_BYTES)  // 61440 B
#define MOE_TOK 8

// ---------------- scratch (static device globals; no allocation) ----------------
__device__ __half g_tokh[MTOK*EMB];            // tokens + pos embed, fp16
__device__ __half g_hnh[MTOK*EMB];             // LN output, fp16
__device__ __half g_xh [MPATCH*768];           // im2col x, fp16
__device__ __half g_cwh[EMB*768];              // conv_w fp16
__device__ __half g_wkh[768*EMB];              // in_proj_w K/V rows fp16
__device__ __half g_kvh[MTOK*768];             // K/V output, fp16
__device__ __half g_ew1h[NE*EMB*HID];          // expert W1 fp16
__device__ __half g_ew2h[NE*HID*EMB];          // expert W2 fp16
__device__ float g_h2 [BATCH*EMB];
__device__ float g_hid[256*HID];
__device__ float g_p2 [4*256*EMB];
__device__ int   g_ecnt[NE];
__device__ int   g_elist[NE*256];

__device__ __forceinline__ float warp_sum(float v) {
#pragma unroll
    for (int o = 16; o > 0; o >>= 1) v += __shfl_down_sync(0xffffffffu, v, o);
    return v;
}
__device__ __forceinline__ float warp_allsum(float v) {
#pragma unroll
    for (int o = 16; o > 0; o >>= 1) v += __shfl_xor_sync(0xffffffffu, v, o);
    return v;
}
__device__ __forceinline__ float warp_allmax(float v) {
#pragma unroll
    for (int o = 16; o > 0; o >>= 1) v = fmaxf(v, __shfl_xor_sync(0xffffffffu, v, o));
    return v;
}
__device__ __forceinline__ float gelu_exact(float v) {
    return 0.5f * v * (1.0f + erff(v * 0.70710678118654752f));
}
__device__ __forceinline__ uint32_t smem_u32(const void* p) {
    uint32_t a;
    asm("{ .reg .u64 t; cvta.to.shared.u64 t, %1; cvt.u32.u64 %0, t; }" : "=r"(a) : "l"(p));
    return a;
}

// mma.sync m16n8k16 fp16 -> f32
__device__ __forceinline__ void mma_f16(float* c, const uint32_t* a, const uint32_t* b) {
    asm volatile(
        "mma.sync.aligned.m16n8k16.row.col.f32.f16.f16.f32 "
        "{%0,%1,%2,%3}, {%4,%5,%6,%7}, {%8,%9}, {%0,%1,%2,%3};"
        : "+f"(c[0]), "+f"(c[1]), "+f"(c[2]), "+f"(c[3])
        : "r"(a[0]), "r"(a[1]), "r"(a[2]), "r"(a[3]), "r"(b[0]), "r"(b[1]));
}
__device__ __forceinline__ void ldsm4(uint32_t* r, uint32_t addr) {
    asm volatile("ldmatrix.sync.aligned.m8n8.x4.shared.b16 {%0,%1,%2,%3}, [%4];"
        : "=r"(r[0]), "=r"(r[1]), "=r"(r[2]), "=r"(r[3]) : "r"(addr));
}
__device__ __forceinline__ void cpa16(uint32_t dst, const void* src) {
    asm volatile("cp.async.cg.shared.global [%0], [%1], 16;" :: "r"(dst), "l"(src));
}
#define CP_COMMIT() asm volatile("cp.async.commit_group;" ::: "memory")
template<int N> __device__ __forceinline__ void cp_wait() {
    asm volatile("cp.async.wait_group %0;" :: "n"(N) : "memory");
}

// pack fp32x4 -> fp16x4
__device__ __forceinline__ uint2 pack4_h(float4 v) {
    uint2 hp;
    __half h0 = __float2half_rn(v.x), h1 = __float2half_rn(v.y);
    __half h2 = __float2half_rn(v.z), h3 = __float2half_rn(v.w);
    hp.x = ((uint32_t)__half_as_ushort(h1) << 16) | __half_as_ushort(h0);
    hp.y = ((uint32_t)__half_as_ushort(h3) << 16) | __half_as_ushort(h2);
    return hp;
}
__device__ __forceinline__ float4 unpack4_h(uint2 hp) {
    float4 v;
    v.x = __half2float(__ushort_as_half((unsigned short)(hp.x & 0xFFFF)));
    v.y = __half2float(__ushort_as_half((unsigned short)(hp.x >> 16)));
    v.z = __half2float(__ushort_as_half((unsigned short)(hp.y & 0xFFFF)));
    v.w = __half2float(__ushort_as_half((unsigned short)(hp.y >> 16)));
    return v;
}

// ---------------- KXW: im2col x + all weight conversion + cls init, one launch ------------
#define N4X (MPATCH*768/4)
#define CW4 (EMB*768/4)
#define WK4 (768*EMB/4)
#define CLS4 (BATCH*EMB/4)
#define E14 (NE*EMB*HID/4)
#define E24 (NE*HID*EMB/4)
__global__ void __launch_bounds__(256) kxw_prep(const float* __restrict__ x,
                                                const float* __restrict__ convw,
                                                const float* __restrict__ inprojw,
                                                const float* __restrict__ cls,
                                                const float* __restrict__ pos,
                                                const float* __restrict__ ew1,
                                                const float* __restrict__ ew2) {
    int idx = blockIdx.x*256 + threadIdx.x;
    if (idx < N4X) {
        int fi = idx*4;
        int w  = fi % 224;
        int t1 = fi / 224;
        int h  = t1 % 224;
        int cb = t1 / 224;
        int c  = cb % 3, b = cb / 3;
        float4 v = *(const float4*)&x[fi];
        int px = w >> 4, j = w & 15, py = h >> 4, i = h & 15;
        int r = b*NPATCH + py*14 + px;
        int k = c*256 + i*16 + j;
        *(uint2*)&g_xh[(size_t)r*768 + k] = pack4_h(v);
        return;
    }
    int i = idx - N4X;
    if (i < CW4) { ((uint2*)g_cwh)[i] = pack4_h(((const float4*)convw)[i]); return; }
    int j = i - CW4;
    if (j < WK4) { ((uint2*)g_wkh)[j] = pack4_h(((const float4*)(inprojw + 384*EMB))[j]); return; }
    int m = j - WK4;
    if (m < CLS4) {
        int b = m / (EMB/4);
        int e4 = m % (EMB/4);
        float4 cv = ((const float4*)cls)[e4];
        float4 pv = ((const float4*)pos)[e4];
        float4 o;
        o.x = cv.x + pv.x; o.y = cv.y + pv.y; o.z = cv.z + pv.z; o.w = cv.w + pv.w;
        ((uint2*)&g_tokh[(size_t)(b*NTOK)*EMB])[e4] = pack4_h(o);
        if (m < NE) g_ecnt[m] = 0;
        return;
    }
    int p = m - CLS4;
    if (p < E14) { ((uint2*)g_ew1h)[p] = pack4_h(((const float4*)ew1)[p]); return; }
    int q = p - E14;
    if (q < E24) ((uint2*)g_ew2h)[q] = pack4_h(((const float4*)ew2)[q]);
}

// ============ HMMA GEMM: 128x128 block, 512 thr / 16 warps (4x4, 32x32 warp tile),
// ============ K-chunk 32, fp16 operands, 3-stage cp.async, 2 CTAs/SM ============

struct GemmCtx {
    int lane, warp, wm, wn;
    uint32_t smb, aoff[2], boff[2];
    int crow, ccol;
};
__device__ __forceinline__ void gemm_init(GemmCtx& g, const void* sm) {
    int tid = threadIdx.x;
    g.lane = tid & 31; g.warp = tid >> 5;
    g.wm = g.warp & 3; g.wn = g.warp >> 2;
    g.smb = smem_u32(sm);
    int r_in = g.lane & 7, g8 = g.lane >> 3;
#pragma unroll
    for (int mf = 0; mf < 2; mf++)
        g.aoff[mf] = ((g.wm*32 + mf*16 + r_in + ((g8 & 1) << 3))*SSTR + ((g8 >> 1) << 3)) * 2;
#pragma unroll
    for (int j = 0; j < 2; j++)
        g.boff[j] = ((g.wn*32 + j*16 + r_in + ((g8 >> 1) << 3))*SSTR + ((g8 & 1) << 3)) * 2;
    g.crow = tid >> 2;
    g.ccol = (tid & 3) * 8;
}
__device__ __forceinline__ void gemm_copy(const GemmCtx& g, int stage,
        const __half* A, size_t a_str, const __half* B, size_t b_str, int k0) {
    uint32_t st = g.smb + (uint32_t)stage*STG_BYTES;
    uint32_t sdst = (uint32_t)(g.crow*SSTR + g.ccol)*2;
    cpa16(st +           sdst, A + (size_t)g.crow*a_str + k0 + g.ccol);
    cpa16(st + 1*TSZ*2 + sdst, B + (size_t)g.crow*b_str + k0 + g.ccol);
    CP_COMMIT();
}
__device__ __forceinline__ void gemm_compute(const GemmCtx& g, int stage, float acc[2][4][4]) {
    uint32_t st = g.smb + (uint32_t)stage*STG_BYTES;
    uint32_t a_b = st, b_b = st + 1*TSZ*2;
#pragma unroll
    for (int kb = 0; kb < 32; kb += 16) {
        uint32_t kbo = kb * 2;
        uint32_t a[2][4], bfr[2][4];
#pragma unroll
        for (int mf = 0; mf < 2; mf++) ldsm4(a[mf], a_b + g.aoff[mf] + kbo);
#pragma unroll
        for (int j = 0; j < 2; j++) ldsm4(bfr[j], b_b + g.boff[j] + kbo);
#pragma unroll
        for (int mf = 0; mf < 2; mf++)
#pragma unroll
            for (int nf = 0; nf < 4; nf++)
                mma_f16(acc[mf][nf], a[mf], &bfr[nf>>1][(nf&1)*2]);
    }
}

// ---------------- K1: patch-embed GEMM on im2col x, fp16 tok output ----------------
__global__ void __launch_bounds__(512, 2) k1_patch_mma(
        const float* __restrict__ convb, const float* __restrict__ pos) {
    extern __shared__ __half sm[];
    GemmCtx g; gemm_init(g, sm);
    int tileM = blockIdx.x * 128;
    int tileN = blockIdx.y * 128;
    const __half *A = g_xh + (size_t)tileM*768;
    const __half *B = g_cwh + (size_t)tileN*768;
    float acc[2][4][4] = {};
    const int C = 24;
    gemm_copy(g, 0, A, 768, B, 768, 0);
    gemm_copy(g, 1, A, 768, B, 768, 32);
    for (int ch = 0; ch < C; ch++) {
        if (ch == C-1) cp_wait<0>(); else cp_wait<1>();
        __syncthreads();
        if (ch + NSTAGE - 1 < C)
            gemm_copy(g, (ch + NSTAGE - 1) % NSTAGE, A, 768, B, 768, (ch + NSTAGE - 1)*32);
        gemm_compute(g, ch % NSTAGE, acc);
    }
#pragma unroll
    for (int mf = 0; mf < 2; mf++) {
#pragma unroll
        for (int nf = 0; nf < 4; nf++) {
            int n = tileN + g.wn*32 + nf*8 + (g.lane & 3)*2;
            float cb0 = convb[n], cb1 = convb[n+1];
#pragma unroll
            for (int h = 0; h < 2; h++) {
                int R = tileM + g.wm*32 + mf*16 + (g.lane >> 2) + h*8;
                int b = R / NPATCH, p = R % NPATCH;
                int tok = b*NTOK + 1 + p;
                float ox = acc[mf][nf][2*h]   + cb0 + pos[(1+p)*EMB + n];
                float oy = acc[mf][nf][2*h+1] + cb1 + pos[(1+p)*EMB + n + 1];
                *(__half2*)&g_tokh[(size_t)tok*EMB + n] = __floats2half2_rn(ox, oy);
            }
        }
    }
}

// ---------------- K3: K/V projection GEMM, fp16 output. M=25216, N=768, K=384 -------------
__global__ void __launch_bounds__(512, 2) k3_kv_mma(const float* __restrict__ bias) {
    extern __shared__ __half sm[];
    GemmCtx g; gemm_init(g, sm);
    int tileM = blockIdx.x * 128;
    int tileN = blockIdx.y * 128;
    const __half *A = g_hnh + (size_t)tileM*EMB;
    const __half *B = g_wkh + (size_t)tileN*EMB;
    float acc[2][4][4] = {};
    const int C = 12;
    gemm_copy(g, 0, A, EMB, B, EMB, 0);
    gemm_copy(g, 1, A, EMB, B, EMB, 32);
    for (int ch = 0; ch < C; ch++) {
        if (ch == C-1) cp_wait<0>(); else cp_wait<1>();
        __syncthreads();
        if (ch + NSTAGE - 1 < C)
            gemm_copy(g, (ch + NSTAGE - 1) % NSTAGE, A, EMB, B, EMB, (ch + NSTAGE - 1)*32);
        gemm_compute(g, ch % NSTAGE, acc);
    }
#pragma unroll
    for (int mf = 0; mf < 2; mf++) {
#pragma unroll
        for (int nf = 0; nf < 4; nf++) {
            int n = tileN + g.wn*32 + nf*8 + (g.lane & 3)*2;
            float b0 = bias[384 + n], b1v = bias[384 + n + 1];
#pragma unroll
            for (int h = 0; h < 2; h++) {
                int R = tileM + g.wm*32 + mf*16 + (g.lane >> 2) + h*8;
                *(__half2*)&g_kvh[(size_t)R*768 + n] =
                    __floats2half2_rn(acc[mf][nf][2*h] + b0, acc[mf][nf][2*h+1] + b1v);
            }
        }
    }
}

// ---------------- K2: LayerNorm, warp per token, fp16 in / fp16 out ----------------
__global__ void __launch_bounds__(256) k2_ln(const float* __restrict__ g,
                                             const float* __restrict__ bt) {
    int t = blockIdx.x * 8 + (threadIdx.x >> 5);
    int lane = threadIdx.x & 31;
    const uint2* in = (const uint2*)(g_tokh + (size_t)t*EMB);
    float4 v[3];
    float s = 0.f, q = 0.f;
#pragma unroll
    for (int j = 0; j < 3; j++) {
        v[j] = unpack4_h(in[lane + 32*j]);
        s += v[j].x + v[j].y + v[j].z + v[j].w;
        q += v[j].x*v[j].x + v[j].y*v[j].y + v[j].z*v[j].z + v[j].w*v[j].w;
    }
    s = warp_allsum(s); q = warp_allsum(q);
    float m = s * (1.0f/EMB);
    float r = rsqrtf(q*(1.0f/EMB) - m*m + 1e-5f);
#pragma unroll
    for (int j = 0; j < 3; j++) {
        float4 gg = ((const float4*)g)[lane + 32*j];
        float4 bb = ((const float4*)bt)[lane + 32*j];
        float4 o;
        o.x = (v[j].x - m)*r*gg.x + bb.x;
        o.y = (v[j].y - m)*r*gg.y + bb.y;
        o.z = (v[j].z - m)*r*gg.z + bb.z;
        o.w = (v[j].w - m)*r*gg.w + bb.w;
        *(uint2*)&g_hnh[(size_t)t*EMB + 4*(lane + 32*j)] = pack4_h(o);
    }
}

// ---------------- K456: q-proj + attention + out_proj + LN + router (fused, block per b) ---
__global__ void __launch_bounds__(EMB) k456_attn(
        const float* __restrict__ W,  const float* __restrict__ bias,
        const float* __restrict__ Wo, const float* __restrict__ bo,
        const float* __restrict__ g1, const float* __restrict__ b1,
        const float* __restrict__ rw, const float* __restrict__ rb) {
    int b = blockIdx.x;
    int tid = threadIdx.x;                        // 384 = 12 warps
    int w = tid >> 5, l = tid & 31;
    __shared__ float hs[EMB], qsm[EMB], osm[EMB], h2s[EMB];
    __shared__ float sc[HEADS][NTOK+1];
    __shared__ float inv_s[HEADS];
    __shared__ float rsx[12], rqx[12];
    __shared__ float lg[NE];
    __shared__ float mm, rr;

    hs[tid] = __half2float(g_hnh[(size_t)(b*NTOK)*EMB + tid]);
    __syncthreads();

    {
        float acc = bias[tid];
        const float4* Wr = (const float4*)(W + (size_t)tid*EMB);
#pragma unroll 8
        for (int k = 0; k < 96; k++) {
            float4 wv = Wr[k];
            acc += hs[4*k]*wv.x + hs[4*k+1]*wv.y + hs[4*k+2]*wv.z + hs[4*k+3]*wv.w;
        }
        qsm[tid] = acc;
    }
    __syncthreads();

    const __half* kvb = g_kvh + (size_t)b*NTOK*768;
    for (int idx = tid; idx < HEADS*NTOK; idx += EMB) {
        int h = idx / NTOK, j = idx % NTOK;
        const __half2* kr = (const __half2*)(kvb + j*768 + h*HD);
        const float* qh = qsm + h*HD;
        float p = 0.f;
#pragma unroll
        for (int d = 0; d < 32; d++) {
            float2 kv2 = __half22float2(kr[d]);
            p += qh[2*d]*kv2.x + qh[2*d+1]*kv2.y;
        }
        sc[h][j] = p * 0.125f;
    }
    __syncthreads();

    if (w < HEADS) {
        float mx = -1e30f;
        for (int j = l; j < NTOK; j += 32) mx = fmaxf(mx, sc[w][j]);
        mx = warp_allmax(mx);
        float sm = 0.f;
        for (int j = l; j < NTOK; j += 32) { float e = expf(sc[w][j] - mx); sc[w][j] = e; sm += e; }
        sm = warp_allsum(sm);
        if (l == 0) inv_s[w] = 1.0f / sm;
    }
    __syncthreads();

    {
        int h = tid >> 6;
        const __half* vb = kvb + 384 + tid;
        const float* ph = sc[h];
        float o = 0.f;
        int j = 0;
#pragma unroll 4
        for (; j + 4 <= NTOK; j += 4) {
            o += ph[j]  *__half2float(vb[(size_t)(j  )*768]);
            o += ph[j+1]*__half2float(vb[(size_t)(j+1)*768]);
            o += ph[j+2]*__half2float(vb[(size_t)(j+2)*768]);
            o += ph[j+3]*__half2float(vb[(size_t)(j+3)*768]);
        }
        for (; j < NTOK; j++) o += ph[j]*__half2float(vb[(size_t)j*768]);
        osm[tid] = o * inv_s[h];
    }
    __syncthreads();

    float acc = bo[tid];
    {
        const float4* Wr = (const float4*)(Wo + (size_t)tid*EMB);
#pragma unroll 8
        for (int k = 0; k < 96; k++) {
            float4 wv = Wr[k];
            acc += osm[4*k]*wv.x + osm[4*k+1]*wv.y + osm[4*k+2]*wv.z + osm[4*k+3]*wv.w;
        }
    }
    float s = warp_sum(acc), q = warp_sum(acc*acc);
    if (l == 0) { rsx[w] = s; rqx[w] = q; }
    __syncthreads();
    if (tid == 0) {
        float S = 0.f, Q = 0.f;
#pragma unroll
        for (int i = 0; i < 12; i++) { S += rsx[i]; Q += rqx[i]; }
        float m = S*(1.0f/EMB);
        mm = m; rr = rsqrtf(Q*(1.0f/EMB) - m*m + 1e-5f);
    }
    __syncthreads();
    float h2 = (acc-mm)*rr*g1[tid] + b1[tid];
    g_h2[b*EMB + tid] = h2;
    h2s[tid] = h2;
    __syncthreads();
    if (w < NE) {
        float p = 0.f;
        for (int e = l; e < EMB; e += 32) p += h2s[e]*rw[w*EMB + e];
        p = warp_sum(p);
        if (l == 0) lg[w] = p + rb[w];
    }
    __syncthreads();
    if (tid == 0) {
        int i1 = 0;
        for (int i = 1; i < NE; i++) if (lg[i] > lg[i1]) i1 = i;
        int i2 = -1;
        for (int i = 0; i < NE; i++) {
            if (i == i1) continue;
            if (i2 < 0 || lg[i] > lg[i2]) i2 = i;
        }
        int p1 = atomicAdd(&g_ecnt[i1], 1);
        g_elist[i1*256 + p1] = b*2;
        int p2 = atomicAdd(&g_ecnt[i2], 1);
        g_elist[i2*256 + p2] = b*2 + 1;
    }
}

// ---------------- K8a: MoE phase 1, fp16 weights ----------------
__global__ void __launch_bounds__(EMB) k8a_moe(const float* __restrict__ eb1) {
    int e = blockIdx.x;
    int tile = blockIdx.y;
    int slice = blockIdx.z;
    int n = g_ecnt[e];
    int t0 = tile * MOE_TOK;
    if (t0 >= n) return;
    int nt = min(MOE_TOK, n - t0);

    __shared__ float hsT[EMB][MOE_TOK];
    __shared__ int ent[MOE_TOK];
    int tid = threadIdx.x;
    if (tid < MOE_TOK)
        ent[tid] = g_elist[e*256 + t0 + ((tid < nt) ? tid : 0)];
    __syncthreads();
#pragma unroll
    for (int tt = 0; tt < MOE_TOK; tt++)
        hsT[tid][tt] = g_h2[(ent[tt] >> 1)*EMB + tid];
    __syncthreads();

    int c = slice*384 + tid;
    const __half* W1 = g_ew1h + (size_t)e*EMB*HID + c;
    float b1v = eb1[e*HID + c];
    float acc[MOE_TOK];
#pragma unroll
    for (int tt = 0; tt < MOE_TOK; tt++) acc[tt] = b1v;
#pragma unroll 8
    for (int k = 0; k < EMB; k++) {
        float w = __half2float(W1[(size_t)k*HID]);
        float4 h0 = *(const float4*)&hsT[k][0];
        float4 h1 = *(const float4*)&hsT[k][4];
        acc[0] += h0.x*w; acc[1] += h0.y*w; acc[2] += h0.z*w; acc[3] += h0.w*w;
        acc[4] += h1.x*w; acc[5] += h1.y*w; acc[6] += h1.z*w; acc[7] += h1.w*w;
    }
#pragma unroll
    for (int tt = 0; tt < MOE_TOK; tt++)
        if (tt < nt)
            g_hid[(size_t)ent[tt]*HID + c] = gelu_exact(acc[tt]);
}

// ---------------- K8b: MoE phase 2, fp16 weights ----------------
__global__ void __launch_bounds__(EMB) k8b_moe(const float* __restrict__ eb2) {
    int e = blockIdx.x;
    int tile = blockIdx.y;
    int slice = blockIdx.z;
    int n = g_ecnt[e];
    int t0 = tile * MOE_TOK;
    if (t0 >= n) return;
    int nt = min(MOE_TOK, n - t0);

    __shared__ float hidT[384][MOE_TOK];
    __shared__ int ent[MOE_TOK];
    int tid = threadIdx.x;
    if (tid < MOE_TOK)
        ent[tid] = g_elist[e*256 + t0 + ((tid < nt) ? tid : 0)];
    __syncthreads();
#pragma unroll
    for (int tt = 0; tt < MOE_TOK; tt++)
        hidT[tid][tt] = g_hid[(size_t)ent[tt]*HID + slice*384 + tid];
    __syncthreads();

    const __half* W2 = g_ew2h + (size_t)e*HID*EMB + (size_t)slice*384*EMB + tid;
    float acc[MOE_TOK] = {};
#pragma unroll 8
    for (int k = 0; k < 384; k++) {
        float w = __half2float(W2[(size_t)k*EMB]);
        float4 h0 = *(const float4*)&hidT[k][0];
        float4 h1 = *(const float4*)&hidT[k][4];
        acc[0] += h0.x*w; acc[1] += h0.y*w; acc[2] += h0.z*w; acc[3] += h0.w*w;
        acc[4] += h1.x*w; acc[5] += h1.y*w; acc[6] += h1.z*w; acc[7] += h1.w*w;
    }
    float b2v = (slice == 0) ? eb2[e*EMB + tid] : 0.f;
#pragma unroll
    for (int tt = 0; tt < MOE_TOK; tt++)
        if (tt < nt)
            g_p2[(size_t)slice*(256*EMB) + ent[tt]*EMB + tid] = 0.5f * (acc[tt] + b2v);
}

// ---------------- K9: LN2 + classification head, 4 tokens/block, class-sliced ----------------
#define K9_TOK 4
__global__ void __launch_bounds__(EMB) k9_head(
        const float* __restrict__ g2, const float* __restrict__ b2,
        const float* __restrict__ Wh, const float* __restrict__ bh,
        float* __restrict__ out) {
    int b0 = blockIdx.x * K9_TOK;
    int cblk = blockIdx.y;
    int tid = threadIdx.x;
    __shared__ float hl[K9_TOK][EMB];
    __shared__ float rsx[K9_TOK][12], rqx[K9_TOK][12];
    __shared__ float mm[K9_TOK], rr[K9_TOK];
    int w = tid >> 5, l = tid & 31;
    float v[K9_TOK];
#pragma unroll
    for (int tt = 0; tt < K9_TOK; tt++) {
        int b = b0 + tt;
        float sum = 0.f;
#pragma unroll
        for (int s = 0; s < 4; s++)
            sum += g_p2[(size_t)s*(256*EMB) + (b*2)*EMB + tid]
                 + g_p2[(size_t)s*(256*EMB) + (b*2+1)*EMB + tid];
        v[tt] = sum;
        float sv = warp_sum(sum), qv = warp_sum(sum*sum);
        if (l == 0) { rsx[tt][w] = sv; rqx[tt][w] = qv; }
    }
    __syncthreads();
    if (tid < K9_TOK) {
        float S = 0.f, Q = 0.f;
#pragma unroll
        for (int i = 0; i < 12; i++) { S += rsx[tid][i]; Q += rqx[tid][i]; }
        float m = S*(1.0f/EMB);
        mm[tid] = m; rr[tid] = rsqrtf(Q*(1.0f/EMB) - m*m + 1e-5f);
    }
    __syncthreads();
    float gv = g2[tid], bv = b2[tid];
#pragma unroll
    for (int tt = 0; tt < K9_TOK; tt++)
        hl[tt][tid] = (v[tt]-mm[tt])*rr[tt]*gv + bv;
    __syncthreads();
    int c = cblk*384 + tid;
    if (c < NCLS) {
        float acc[K9_TOK];
        float bhc = bh[c];
#pragma unroll
        for (int tt = 0; tt < K9_TOK; tt++) acc[tt] = bhc;
        const float4* Wr = (const float4*)(Wh + (size_t)c*EMB);
#pragma unroll 4
        for (int k = 0; k < 96; k++) {
            float4 wv = Wr[k];
#pragma unroll
            for (int tt = 0; tt < K9_TOK; tt++)
                acc[tt] += hl[tt][4*k]*wv.x + hl[tt][4*k+1]*wv.y
                         + hl[tt][4*k+2]*wv.z + hl[tt][4*k+3]*wv.w;
        }
#pragma unroll
        for (int tt = 0; tt < K9_TOK; tt++)
            out[(b0+tt)*NCLS + c] = acc[tt];
    }
}

// ---------------- launcher ----------------
extern "C" void kernel_launch(void* const* d_in, const int* in_sizes, int n_in,
                              void* d_out, int out_size) {
    const float* x         = (const float*)d_in[0];
    const float* conv_w    = (const float*)d_in[1];
    const float* conv_b    = (const float*)d_in[2];
    const float* cls_token = (const float*)d_in[3];
    const float* pos_embed = (const float*)d_in[4];
    const float* ln1_g     = (const float*)d_in[5];
    const float* ln1_b     = (const float*)d_in[6];
    const float* in_proj_w = (const float*)d_in[7];
    const float* in_proj_b = (const float*)d_in[8];
    const float* out_proj_w= (const float*)d_in[9];
    const float* out_proj_b= (const float*)d_in[10];
    const float* router_w  = (const float*)d_in[11];
    const float* router_b  = (const float*)d_in[12];
    const float* ew1       = (const float*)d_in[13];
    const float* eb1       = (const float*)d_in[14];
    const float* ew2       = (const float*)d_in[15];
    const float* eb2       = (const float*)d_in[16];
    const float* ln2_g     = (const float*)d_in[17];
    const float* ln2_b     = (const float*)d_in[18];
    const float* head_w    = (const float*)d_in[19];
    const float* head_b    = (const float*)d_in[20];
    float* out = (float*)d_out;

    cudaFuncSetAttribute(k1_patch_mma, cudaFuncAttributeMaxDynamicSharedMemorySize, SMEM_GEMM);
    cudaFuncSetAttribute(k3_kv_mma,    cudaFuncAttributeMaxDynamicSharedMemorySize, SMEM_GEMM);

    kxw_prep<<<(N4X + CW4 + WK4 + CLS4 + E14 + E24 + 255)/256, 256>>>(
        x, conv_w, in_proj_w, cls_token, pos_embed, ew1, ew2);
    k1_patch_mma<<<dim3(MPATCH/128, EMB/128), 512, SMEM_GEMM>>>(conv_b, pos_embed);
    k2_ln<<<MTOK/8, 256>>>(ln1_g, ln1_b);
    k3_kv_mma<<<dim3(MTOK/128, 768/128), 512, SMEM_GEMM>>>(in_proj_b);
    k456_attn<<<BATCH, EMB>>>(in_proj_w, in_proj_b, out_proj_w, out_proj_b,
                              ln1_g, ln1_b, router_w, router_b);
    k8a_moe<<<dim3(NE, 256/MOE_TOK, 4), EMB>>>(eb1);
    k8b_moe<<<dim3(NE, 256/MOE_TOK, 4), EMB>>>(eb2);
    k9_head<<<dim3(BATCH/K9_TOK, 3), EMB>>>(ln2_g, ln2_b, head_w, head_b, out);
}